// round 5
// baseline (speedup 1.0000x reference)
#include <cuda_runtime.h>
#include <cuda_bf16.h>
#include <cstdint>

#define NB 16
#define NT 64
#define NN 128

// ---- packed global operands (hi/lo bf16x2 planes) --------------------------
__device__ uint32_t g_SB[2048u * 16384u];      // S  B-fmt  [tile(b,t,e)][plane][n*64+kp]
__device__ uint32_t g_xA[1024u * 8192u];       // x  A-fmt  [tile(b,t)][plane][r*64+kp]
__device__ uint32_t g_xB[1024u * 8192u];       // x  B64    [tile(b,t)][plane][n*32+kpf]
__device__ uint32_t g_tapA[2][2048u * 8192u];  // taps 1,2 A-fmt per (b,t,e)
__device__ uint32_t g_tapB[3][2048u * 8192u];  // taps 1,2,3 B64 per (b,t,e)
__device__ uint32_t g_HA[7u * 4096u];          // H chunks A64: c0 = k0 e-summed; c1..6 = (e,k>=1)

// ---------------------------------------------------------------------------
__device__ __forceinline__ uint32_t pack_hi2(float a, float b) {
    uint32_t ua = (uint32_t)__bfloat16_as_ushort(__float2bfloat16(a));
    uint32_t ub = (uint32_t)__bfloat16_as_ushort(__float2bfloat16(b));
    return (ub << 16) | ua;
}
__device__ __forceinline__ uint32_t pack_lo2(float a, float b) {
    __nv_bfloat16 ha = __float2bfloat16(a);
    __nv_bfloat16 hb = __float2bfloat16(b);
    float ra = a - __bfloat162float(ha);
    float rb = b - __bfloat162float(hb);
    uint32_t ua = (uint32_t)__bfloat16_as_ushort(__float2bfloat16(ra));
    uint32_t ub = (uint32_t)__bfloat16_as_ushort(__float2bfloat16(rb));
    return (ub << 16) | ua;
}

#define MMA_BF16(c, a0, a1, a2, a3, b0, b1)                                   \
    asm volatile(                                                             \
        "mma.sync.aligned.m16n8k16.row.col.f32.bf16.bf16.f32 "                \
        "{%0,%1,%2,%3}, {%4,%5,%6,%7}, {%8,%9}, {%0,%1,%2,%3};"               \
        : "+f"((c)[0]), "+f"((c)[1]), "+f"((c)[2]), "+f"((c)[3])              \
        : "r"(a0), "r"(a1), "r"(a2), "r"(a3), "r"(b0), "r"(b1))

// ---- MMA cores (smem strides: 68 for 128-K fmt, 36 for 64-K fmt) -----------
__device__ __forceinline__ void mma_fullK(const uint32_t* sm, int AHI, int ALO,
                                          int SBH, int SBL, float acc[8][4],
                                          int wm, int wn, int ra, int ca)
{
    #pragma unroll
    for (int nt = 0; nt < 8; nt++)
        acc[nt][0] = acc[nt][1] = acc[nt][2] = acc[nt][3] = 0.f;
    #pragma unroll
    for (int k = 0; k < 8; k++) {
        int ab = AHI + (16 * wm + ra) * 68 + k * 8 + ca;
        uint32_t ah0 = sm[ab],     ah1 = sm[ab + 8 * 68];
        uint32_t ah2 = sm[ab + 4], ah3 = sm[ab + 8 * 68 + 4];
        int al = ab + (ALO - AHI);
        uint32_t al0 = sm[al],     al1 = sm[al + 8 * 68];
        uint32_t al2 = sm[al + 4], al3 = sm[al + 8 * 68 + 4];
        #pragma unroll
        for (int nt = 0; nt < 8; nt++) {
            int bb = SBH + (64 * wn + nt * 8 + ra) * 68 + k * 8 + ca;
            uint32_t bh0 = sm[bb], bh1 = sm[bb + 4];
            uint32_t bl0 = sm[bb + (SBL - SBH)], bl1 = sm[bb + (SBL - SBH) + 4];
            MMA_BF16(acc[nt], ah0, ah1, ah2, ah3, bh0, bh1);
            MMA_BF16(acc[nt], ah0, ah1, ah2, ah3, bl0, bl1);
            MMA_BF16(acc[nt], al0, al1, al2, al3, bh0, bh1);
        }
    }
}
__device__ __forceinline__ void mma_halfK(const uint32_t* sm, float accY[8][4],
                                          int HAH, int HAL, int ZH, int ZL,
                                          int wm, int wn, int ra, int ca)
{
    #pragma unroll
    for (int kk = 0; kk < 4; kk++) {
        int ab = HAH + (16 * wm + ra) * 36 + kk * 8 + ca;
        uint32_t ah0 = sm[ab],     ah1 = sm[ab + 8 * 36];
        uint32_t ah2 = sm[ab + 4], ah3 = sm[ab + 8 * 36 + 4];
        int al = ab + (HAL - HAH);
        uint32_t al0 = sm[al],     al1 = sm[al + 8 * 36];
        uint32_t al2 = sm[al + 4], al3 = sm[al + 8 * 36 + 4];
        #pragma unroll
        for (int nt = 0; nt < 8; nt++) {
            int bb = ZH + (64 * wn + nt * 8 + ra) * 36 + kk * 8 + ca;
            uint32_t bh0 = sm[bb], bh1 = sm[bb + 4];
            uint32_t bl0 = sm[bb + (ZL - ZH)], bl1 = sm[bb + (ZL - ZH) + 4];
            MMA_BF16(accY[nt], ah0, ah1, ah2, ah3, bh0, bh1);
            MMA_BF16(accY[nt], ah0, ah1, ah2, ah3, bl0, bl1);
            MMA_BF16(accY[nt], al0, al1, al2, al3, bh0, bh1);
        }
    }
}

// ---- acc -> smem staging ---------------------------------------------------
__device__ __forceinline__ void conv_A(uint32_t* sm, int AHI, int ALO,
                                       const float acc[8][4], int wm, int wn, int ra, int ca)
{
    int r0 = 16 * wm + ra;
    #pragma unroll
    for (int nt = 0; nt < 8; nt++) {
        int kp = 32 * wn + 4 * nt + ca;
        sm[AHI + r0 * 68 + kp]       = pack_hi2(acc[nt][0], acc[nt][1]);
        sm[ALO + r0 * 68 + kp]       = pack_lo2(acc[nt][0], acc[nt][1]);
        sm[AHI + (r0 + 8) * 68 + kp] = pack_hi2(acc[nt][2], acc[nt][3]);
        sm[ALO + (r0 + 8) * 68 + kp] = pack_lo2(acc[nt][2], acc[nt][3]);
    }
}
__device__ __forceinline__ void conv_ZB(uint32_t* sm, int ZH, int ZL,
                                        const float acc[8][4], int wm, int wn, int ra, int ca)
{
    #pragma unroll
    for (int nt = 0; nt < 8; nt++) {
        float o0 = __shfl_down_sync(0xffffffffu, acc[nt][0], 4);
        float o1 = __shfl_down_sync(0xffffffffu, acc[nt][1], 4);
        float o2 = __shfl_down_sync(0xffffffffu, acc[nt][2], 4);
        float o3 = __shfl_down_sync(0xffffffffu, acc[nt][3], 4);
        if (!(ra & 1)) {
            int c  = 64 * wn + nt * 8 + 2 * ca;
            int ka = 8 * wm + (ra >> 1);
            sm[ZH + c * 36 + ka]           = pack_hi2(acc[nt][0], o0);
            sm[ZL + c * 36 + ka]           = pack_lo2(acc[nt][0], o0);
            sm[ZH + (c + 1) * 36 + ka]     = pack_hi2(acc[nt][1], o1);
            sm[ZL + (c + 1) * 36 + ka]     = pack_lo2(acc[nt][1], o1);
            sm[ZH + c * 36 + ka + 4]       = pack_hi2(acc[nt][2], o2);
            sm[ZL + c * 36 + ka + 4]       = pack_lo2(acc[nt][2], o2);
            sm[ZH + (c + 1) * 36 + ka + 4] = pack_hi2(acc[nt][3], o3);
            sm[ZL + (c + 1) * 36 + ka + 4] = pack_lo2(acc[nt][3], o3);
        }
    }
}

// ===========================================================================
// Prep kernels: convert once
// ===========================================================================
__global__ void __launch_bounds__(256) conv_S_k(const float* __restrict__ S)
{
    extern __shared__ __align__(16) char smraw[];
    float* smT = (float*)smraw;                 // [128][130]
    int tile = blockIdx.x, tid = threadIdx.x;
    const float* Sp = S + (size_t)tile * 16384;
    for (int i = tid; i < 16384; i += 256) {
        int j = i >> 7, n = i & 127;
        smT[n * 130 + j] = Sp[i];
    }
    __syncthreads();
    uint32_t* dst = g_SB + (size_t)tile * 16384;
    for (int w = tid; w < 8192; w += 256) {
        int n = w >> 6, kp = w & 63;
        float2 v = *(const float2*)&smT[n * 130 + 2 * kp];
        dst[w]        = pack_hi2(v.x, v.y);     // n*64+kp == w
        dst[8192 + w] = pack_lo2(v.x, v.y);
    }
}

__global__ void __launch_bounds__(256) conv_x_k(const float* __restrict__ x)
{
    __shared__ float smT[128 * 66];
    int tile = blockIdx.x, tid = threadIdx.x;
    const float* xp = x + (size_t)tile * 8192;
    // A-format (direct)
    uint32_t* da = g_xA + (size_t)tile * 8192;
    for (int w = tid; w < 4096; w += 256) {
        int r = w >> 6, kp = w & 63;
        float2 v = *(const float2*)(xp + r * NN + 2 * kp);
        da[w]        = pack_hi2(v.x, v.y);
        da[4096 + w] = pack_lo2(v.x, v.y);
    }
    // B64-format via transpose
    for (int i = tid; i < 8192; i += 256) {
        int r = i >> 7, n = i & 127;
        smT[n * 66 + r] = xp[i];
    }
    __syncthreads();
    uint32_t* db = g_xB + (size_t)tile * 8192;
    for (int w = tid; w < 4096; w += 256) {
        int n = w >> 5, kpf = w & 31;
        float2 v = *(const float2*)&smT[n * 66 + 2 * kpf];
        db[w]        = pack_hi2(v.x, v.y);      // n*32+kpf == w
        db[4096 + w] = pack_lo2(v.x, v.y);
    }
}

__global__ void __launch_bounds__(256) conv_H_k(const float* __restrict__ H)
{
    int tid = threadIdx.x;
    for (int w = tid; w < 7 * 2048; w += 256) {
        int c = w >> 11, o = (w >> 5) & 63, kpf = w & 31;
        float a, b2;
        if (c == 0) {
            a  = H[o * 512 + 2 * kpf]     + H[o * 512 + 256 + 2 * kpf];
            b2 = H[o * 512 + 2 * kpf + 1] + H[o * 512 + 256 + 2 * kpf + 1];
        } else {
            int e = (c - 1) / 3, k = (c - 1) % 3 + 1;
            int off = e * 256 + k * 64;
            a  = H[o * 512 + off + 2 * kpf];
            b2 = H[o * 512 + off + 2 * kpf + 1];
        }
        g_HA[c * 4096 + (w & 2047)]        = pack_hi2(a, b2);
        g_HA[c * 4096 + 2048 + (w & 2047)] = pack_lo2(a, b2);
    }
}

// ===========================================================================
// Diffusion pass: tap[p+1][b,t,e] = A_in[b,t-1] @ S[b,t,e]
// smem: SBH 0 (8704) | SBL 8704 | AH 17408 (4352) | AL 21760   = 104448 B
// stage after MMA: A-fmt reuses AH/AL; ZB stage (ZH 0, ZL 4608) reuses SB.
// ===========================================================================
#define D_SBH 0
#define D_SBL 8704
#define D_AH  17408
#define D_AL  21760
#define D_SMEM_B ((17408 + 2 * 4352) * 4)

__global__ void __launch_bounds__(256) diffuse_k(int pass)
{
    extern __shared__ __align__(16) char smraw[];
    uint32_t* sm = (uint32_t*)smraw;
    int tile = blockIdx.x, tid = threadIdx.x;
    int e = tile & 1, t = (tile >> 1) & 63, b = tile >> 7;

    if (t == 0) {
        uint4 z = make_uint4(0, 0, 0, 0);
        uint4* tb = (uint4*)(g_tapB[pass] + (size_t)tile * 8192);
        for (int w = tid; w < 512; w += 256) tb[w] = z;
        if (pass < 2) {
            uint4* ta = (uint4*)(g_tapA[pass] + (size_t)tile * 8192);
            for (int w = tid; w < 512; w += 256) ta[w] = z;
        }
        return;
    }

    // fills: pure uint4 copies
    const uint4* sbsrc = (const uint4*)(g_SB + (size_t)tile * 16384);
    for (int w = tid; w < 2048; w += 256) {
        int n = w >> 4, q = w & 15;
        *(uint4*)&sm[D_SBH + n * 68 + 4 * q] = sbsrc[w];
    }
    for (int w = tid; w < 2048; w += 256) {
        int n = w >> 4, q = w & 15;
        *(uint4*)&sm[D_SBL + n * 68 + 4 * q] = sbsrc[2048 + w];
    }
    const uint4* asrc = (pass == 0)
        ? (const uint4*)(g_xA + (size_t)(b * 64 + (t - 1)) * 8192)
        : (const uint4*)(g_tapA[pass - 1] + (size_t)((b * 64 + (t - 1)) * 2 + e) * 8192);
    for (int w = tid; w < 1024; w += 256) {
        int r = w >> 4, q = w & 15;
        *(uint4*)&sm[D_AH + r * 68 + 4 * q] = asrc[w];
    }
    for (int w = tid; w < 1024; w += 256) {
        int r = w >> 4, q = w & 15;
        *(uint4*)&sm[D_AL + r * 68 + 4 * q] = asrc[1024 + w];
    }
    __syncthreads();

    int wid = tid >> 5, lane = tid & 31;
    int wm = wid & 3, wn = wid >> 2;
    int ra = lane >> 2, ca = lane & 3;

    float macc[8][4];
    mma_fullK(sm, D_AH, D_AL, D_SBH, D_SBL, macc, wm, wn, ra, ca);
    __syncthreads();

    if (pass < 2) conv_A(sm, D_AH, D_AL, macc, wm, wn, ra, ca);
    conv_ZB(sm, 0, 4608, macc, wm, wn, ra, ca);
    __syncthreads();

    if (pass < 2) {
        uint4* ta = (uint4*)(g_tapA[pass] + (size_t)tile * 8192);
        for (int w = tid; w < 1024; w += 256) {
            int r = w >> 4, q = w & 15;
            ta[w]        = *(const uint4*)&sm[D_AH + r * 68 + 4 * q];
            ta[1024 + w] = *(const uint4*)&sm[D_AL + r * 68 + 4 * q];
        }
    }
    uint4* tb = (uint4*)(g_tapB[pass] + (size_t)tile * 8192);
    for (int w = tid; w < 1024; w += 256) {
        int n = w >> 3, q = w & 7;
        tb[w]        = *(const uint4*)&sm[0    + n * 36 + 4 * q];
        tb[1024 + w] = *(const uint4*)&sm[4608 + n * 36 + 4 * q];
    }
}

// ===========================================================================
// Projection: accY += HA(c) @ ZB(c) over 7 chunks; y = accY + bias
// smem: HAH 0 (2304) | HAL 2304 | ZH 4608 (4608) | ZL 9216   = 55296 B
// ===========================================================================
#define P_HAH 0
#define P_HAL 2304
#define P_ZH  4608
#define P_ZL  9216
#define P_SMEM_B (13824 * 4)

__global__ void __launch_bounds__(256) proj_k(const float* __restrict__ bias,
                                              float* __restrict__ y)
{
    extern __shared__ __align__(16) char smraw[];
    uint32_t* sm = (uint32_t*)smraw;
    int t = blockIdx.x & 63, b = blockIdx.x >> 6;
    int tid = threadIdx.x;
    int wid = tid >> 5, lane = tid & 31;
    int wm = wid & 3, wn = wid >> 2;
    int ra = lane >> 2, ca = lane & 3;

    float accY[8][4];
    #pragma unroll
    for (int nt = 0; nt < 8; nt++)
        accY[nt][0] = accY[nt][1] = accY[nt][2] = accY[nt][3] = 0.f;

    for (int c = 0; c < 7; c++) {
        if (c) __syncthreads();
        // HA copy
        const uint4* hsrc = (const uint4*)(g_HA + (size_t)c * 4096);
        for (int w = tid; w < 512; w += 256) {
            int o = w >> 3, q = w & 7;
            *(uint4*)&sm[P_HAH + o * 36 + 4 * q] = hsrc[w];
            *(uint4*)&sm[P_HAL + o * 36 + 4 * q] = hsrc[512 + w];
        }
        // ZB copy
        const uint4* zsrc;
        if (c == 0) {
            zsrc = (const uint4*)(g_xB + (size_t)(b * 64 + t) * 8192);
        } else {
            int e = (c - 1) / 3, k = (c - 1) % 3 + 1;
            zsrc = (const uint4*)(g_tapB[k - 1] + (size_t)((b * 64 + t) * 2 + e) * 8192);
        }
        for (int w = tid; w < 1024; w += 256) {
            int n = w >> 3, q = w & 7;
            *(uint4*)&sm[P_ZH + n * 36 + 4 * q] = zsrc[w];
            *(uint4*)&sm[P_ZL + n * 36 + 4 * q] = zsrc[1024 + w];
        }
        __syncthreads();
        mma_halfK(sm, accY, P_HAH, P_HAL, P_ZH, P_ZL, wm, wn, ra, ca);
    }

    float* yp = y + (size_t)(b * 64 + t) * 64 * NN;
    int r0 = 16 * wm + ra;
    float bv0 = bias[r0], bv1 = bias[r0 + 8];
    #pragma unroll
    for (int nt = 0; nt < 8; nt++) {
        int cc = 64 * wn + nt * 8 + 2 * ca;
        *(float2*)(yp + r0 * NN + cc) =
            make_float2(accY[nt][0] + bv0, accY[nt][1] + bv0);
        *(float2*)(yp + (r0 + 8) * NN + cc) =
            make_float2(accY[nt][2] + bv1, accY[nt][3] + bv1);
    }
}

// ---------------------------------------------------------------------------
extern "C" void kernel_launch(void* const* d_in, const int* in_sizes, int n_in,
                              void* d_out, int out_size)
{
    const float* x    = (const float*)d_in[0];
    const float* S    = (const float*)d_in[1];
    const float* H    = (const float*)d_in[2];
    const float* bias = (const float*)d_in[3];
    float* y = (float*)d_out;

    cudaFuncSetAttribute(conv_S_k, cudaFuncAttributeMaxDynamicSharedMemorySize, 128 * 130 * 4);
    cudaFuncSetAttribute(diffuse_k, cudaFuncAttributeMaxDynamicSharedMemorySize, D_SMEM_B);
    cudaFuncSetAttribute(proj_k, cudaFuncAttributeMaxDynamicSharedMemorySize, P_SMEM_B);

    conv_S_k<<<2048, 256, 128 * 130 * 4>>>(S);
    conv_x_k<<<1024, 256>>>(x);
    conv_H_k<<<1, 256>>>(H);

    diffuse_k<<<2048, 256, D_SMEM_B>>>(0);
    diffuse_k<<<2048, 256, D_SMEM_B>>>(1);
    diffuse_k<<<2048, 256, D_SMEM_B>>>(2);

    proj_k<<<1024, 256, P_SMEM_B>>>(bias, y);
}

// round 6
// speedup vs baseline: 1.1529x; 1.1529x over previous
#include <cuda_runtime.h>
#include <cuda_bf16.h>
#include <cstdint>

#define NN 128

// ---- packed global operands (hi/lo bf16x2 planes) --------------------------
__device__ uint32_t g_xA[1024u * 8192u];  // x A-fmt  [tile(b,t)]: hi r*64+kp (4096), lo +4096
__device__ uint32_t g_xB[1024u * 8192u];  // x B64    [tile(b,t)]: hi n*32+kpf (4096), lo +4096
__device__ uint32_t g_HA[8u * 4096u];     // H chunks [e*4+k]: hi o*32+kpf (2048), lo +2048

// ---- smem word offsets -----------------------------------------------------
#define SBH  0          // S B-fmt hi: [128 n][stride 68]
#define SBL  8704
#define M1H  17408      // tap1 A-fmt hi: [64 r][stride 68]
#define M1L  21760
#define M2H  26112
#define M2L  30464
#define ZBH  34816      // tap B64: [128 n][stride 36]
#define ZBL  39424
#define RAWW 44032      // raw fp32 S rows 0..63: [64][128]
#define SMWORDS 52224   // 208896 bytes

// ---------------------------------------------------------------------------
__device__ __forceinline__ uint32_t pack_hi2(float a, float b) {
    uint32_t ua = (uint32_t)__bfloat16_as_ushort(__float2bfloat16(a));
    uint32_t ub = (uint32_t)__bfloat16_as_ushort(__float2bfloat16(b));
    return (ub << 16) | ua;
}
__device__ __forceinline__ uint32_t pack_lo2(float a, float b) {
    __nv_bfloat16 ha = __float2bfloat16(a);
    __nv_bfloat16 hb = __float2bfloat16(b);
    float ra = a - __bfloat162float(ha);
    float rb = b - __bfloat162float(hb);
    uint32_t ua = (uint32_t)__bfloat16_as_ushort(__float2bfloat16(ra));
    uint32_t ub = (uint32_t)__bfloat16_as_ushort(__float2bfloat16(rb));
    return (ub << 16) | ua;
}
__device__ __forceinline__ uint32_t smem_u32(const void* p) {
    uint32_t a;
    asm("{ .reg .u64 t; cvta.to.shared.u64 t, %1; cvt.u32.u64 %0, t; }" : "=r"(a) : "l"(p));
    return a;
}

#define MMA_BF16(c, a0, a1, a2, a3, b0, b1)                                   \
    asm volatile(                                                             \
        "mma.sync.aligned.m16n8k16.row.col.f32.bf16.bf16.f32 "                \
        "{%0,%1,%2,%3}, {%4,%5,%6,%7}, {%8,%9}, {%0,%1,%2,%3};"               \
        : "+f"((c)[0]), "+f"((c)[1]), "+f"((c)[2]), "+f"((c)[3])              \
        : "r"(a0), "r"(a1), "r"(a2), "r"(a3), "r"(b0), "r"(b1))

// ---- S tile fills ----------------------------------------------------------
__device__ __forceinline__ void fill_SB_direct(uint32_t* sm, const float* __restrict__ Sp, int tid) {
    for (int i = tid; i < 8192; i += 256) {
        int n = i & 127, kp = i >> 7;
        float a = Sp[(2 * kp) * NN + n];
        float b = Sp[(2 * kp + 1) * NN + n];
        sm[SBH + n * 68 + kp] = pack_hi2(a, b);
        sm[SBL + n * 68 + kp] = pack_lo2(a, b);
    }
}
// lower 64 rows from RAW (prefetched), upper 64 from global
__device__ __forceinline__ void fill_SB_mixed(uint32_t* sm, const float* __restrict__ Sp, int tid) {
    const float* raw = (const float*)(sm + RAWW);
    for (int i = tid; i < 4096; i += 256) {
        int n = i & 127, kp = i >> 7;               // kp 0..31
        float a = raw[(2 * kp) * NN + n];
        float b = raw[(2 * kp + 1) * NN + n];
        sm[SBH + n * 68 + kp] = pack_hi2(a, b);
        sm[SBL + n * 68 + kp] = pack_lo2(a, b);
    }
    for (int i = tid; i < 4096; i += 256) {
        int n = i & 127, kp = 32 + (i >> 7);        // kp 32..63
        float a = Sp[(2 * kp) * NN + n];
        float b = Sp[(2 * kp + 1) * NN + n];
        sm[SBH + n * 68 + kp] = pack_hi2(a, b);
        sm[SBL + n * 68 + kp] = pack_lo2(a, b);
    }
}
__device__ __forceinline__ void prefetch_S(uint32_t rawb, const float* __restrict__ src, int tid) {
    for (int w = tid; w < 2048; w += 256)
        asm volatile("cp.async.cg.shared.global [%0], [%1], 16;"
                     :: "r"(rawb + (uint32_t)w * 16u), "l"(src + 4 * w));
    asm volatile("cp.async.commit_group;");
}
#define CP_WAIT() asm volatile("cp.async.wait_group 0;" ::: "memory")

// ---- MMA cores -------------------------------------------------------------
// acc = A(smem M-slot, stride 68) @ SB  (3-MMA split)
__device__ __forceinline__ void mma_fullK_sA(const uint32_t* sm, int AHI, int ALO,
                                             float acc[8][4], int wm, int wn, int ra, int ca)
{
    #pragma unroll
    for (int nt = 0; nt < 8; nt++)
        acc[nt][0] = acc[nt][1] = acc[nt][2] = acc[nt][3] = 0.f;
    #pragma unroll
    for (int k = 0; k < 8; k++) {
        int ab = AHI + (16 * wm + ra) * 68 + k * 8 + ca;
        uint32_t ah0 = sm[ab],     ah1 = sm[ab + 8 * 68];
        uint32_t ah2 = sm[ab + 4], ah3 = sm[ab + 8 * 68 + 4];
        int al = ab + (ALO - AHI);
        uint32_t al0 = sm[al],     al1 = sm[al + 8 * 68];
        uint32_t al2 = sm[al + 4], al3 = sm[al + 8 * 68 + 4];
        #pragma unroll
        for (int nt = 0; nt < 8; nt++) {
            int bb = SBH + (64 * wn + nt * 8 + ra) * 68 + k * 8 + ca;
            uint32_t bh0 = sm[bb], bh1 = sm[bb + 4];
            uint32_t bl0 = sm[bb + (SBL - SBH)], bl1 = sm[bb + (SBL - SBH) + 4];
            MMA_BF16(acc[nt], ah0, ah1, ah2, ah3, bh0, bh1);
            MMA_BF16(acc[nt], ah0, ah1, ah2, ah3, bl0, bl1);
            MMA_BF16(acc[nt], al0, al1, al2, al3, bh0, bh1);
        }
    }
}
// acc = A(global g_xA tile, stride 64) @ SB
__device__ __forceinline__ void mma_fullK_gA(const uint32_t* sm, const uint32_t* __restrict__ gx,
                                             float acc[8][4], int wm, int wn, int ra, int ca)
{
    #pragma unroll
    for (int nt = 0; nt < 8; nt++)
        acc[nt][0] = acc[nt][1] = acc[nt][2] = acc[nt][3] = 0.f;
    #pragma unroll
    for (int k = 0; k < 8; k++) {
        int ab = (16 * wm + ra) * 64 + k * 8 + ca;
        uint32_t ah0 = gx[ab],     ah1 = gx[ab + 512];
        uint32_t ah2 = gx[ab + 4], ah3 = gx[ab + 516];
        uint32_t al0 = gx[ab + 4096],     al1 = gx[ab + 4608];
        uint32_t al2 = gx[ab + 4100], al3 = gx[ab + 4612];
        #pragma unroll
        for (int nt = 0; nt < 8; nt++) {
            int bb = SBH + (64 * wn + nt * 8 + ra) * 68 + k * 8 + ca;
            uint32_t bh0 = sm[bb], bh1 = sm[bb + 4];
            uint32_t bl0 = sm[bb + (SBL - SBH)], bl1 = sm[bb + (SBL - SBH) + 4];
            MMA_BF16(acc[nt], ah0, ah1, ah2, ah3, bh0, bh1);
            MMA_BF16(acc[nt], ah0, ah1, ah2, ah3, bl0, bl1);
            MMA_BF16(acc[nt], al0, al1, al2, al3, bh0, bh1);
        }
    }
}
// accY += H-chunk(global, stride 32) @ ZB(smem, stride 36)
__device__ __forceinline__ void mma_halfK_gH(const uint32_t* sm, const uint32_t* __restrict__ gh,
                                             float accY[8][4], int wm, int wn, int ra, int ca)
{
    #pragma unroll
    for (int kk = 0; kk < 4; kk++) {
        int ab = (16 * wm + ra) * 32 + kk * 8 + ca;
        uint32_t ah0 = gh[ab],     ah1 = gh[ab + 256];
        uint32_t ah2 = gh[ab + 4], ah3 = gh[ab + 260];
        uint32_t al0 = gh[ab + 2048], al1 = gh[ab + 2304];
        uint32_t al2 = gh[ab + 2052], al3 = gh[ab + 2308];
        #pragma unroll
        for (int nt = 0; nt < 8; nt++) {
            int bb = ZBH + (64 * wn + nt * 8 + ra) * 36 + kk * 8 + ca;
            uint32_t bh0 = sm[bb], bh1 = sm[bb + 4];
            uint32_t bl0 = sm[bb + (ZBL - ZBH)], bl1 = sm[bb + (ZBL - ZBH) + 4];
            MMA_BF16(accY[nt], ah0, ah1, ah2, ah3, bh0, bh1);
            MMA_BF16(accY[nt], ah0, ah1, ah2, ah3, bl0, bl1);
            MMA_BF16(accY[nt], al0, al1, al2, al3, bh0, bh1);
        }
    }
}

// ---- acc -> smem staging ---------------------------------------------------
__device__ __forceinline__ void conv_A(uint32_t* sm, int AHI, int ALO,
                                       const float acc[8][4], int wm, int wn, int ra, int ca)
{
    int r0 = 16 * wm + ra;
    #pragma unroll
    for (int nt = 0; nt < 8; nt++) {
        int kp = 32 * wn + 4 * nt + ca;
        sm[AHI + r0 * 68 + kp]       = pack_hi2(acc[nt][0], acc[nt][1]);
        sm[ALO + r0 * 68 + kp]       = pack_lo2(acc[nt][0], acc[nt][1]);
        sm[AHI + (r0 + 8) * 68 + kp] = pack_hi2(acc[nt][2], acc[nt][3]);
        sm[ALO + (r0 + 8) * 68 + kp] = pack_lo2(acc[nt][2], acc[nt][3]);
    }
}
__device__ __forceinline__ void conv_ZB(uint32_t* sm, const float acc[8][4],
                                        int wm, int wn, int ra, int ca)
{
    #pragma unroll
    for (int nt = 0; nt < 8; nt++) {
        float o0 = __shfl_down_sync(0xffffffffu, acc[nt][0], 4);
        float o1 = __shfl_down_sync(0xffffffffu, acc[nt][1], 4);
        float o2 = __shfl_down_sync(0xffffffffu, acc[nt][2], 4);
        float o3 = __shfl_down_sync(0xffffffffu, acc[nt][3], 4);
        if (!(ra & 1)) {
            int c  = 64 * wn + nt * 8 + 2 * ca;
            int ka = 8 * wm + (ra >> 1);
            sm[ZBH + c * 36 + ka]           = pack_hi2(acc[nt][0], o0);
            sm[ZBL + c * 36 + ka]           = pack_lo2(acc[nt][0], o0);
            sm[ZBH + (c + 1) * 36 + ka]     = pack_hi2(acc[nt][1], o1);
            sm[ZBL + (c + 1) * 36 + ka]     = pack_lo2(acc[nt][1], o1);
            sm[ZBH + c * 36 + ka + 4]       = pack_hi2(acc[nt][2], o2);
            sm[ZBL + c * 36 + ka + 4]       = pack_lo2(acc[nt][2], o2);
            sm[ZBH + (c + 1) * 36 + ka + 4] = pack_hi2(acc[nt][3], o3);
            sm[ZBL + (c + 1) * 36 + ka + 4] = pack_lo2(acc[nt][3], o3);
        }
    }
}
__device__ __forceinline__ void copy_ZB(uint32_t* sm, const uint32_t* __restrict__ src, int tid) {
    const uint4* s4 = (const uint4*)src;
    for (int w = tid; w < 1024; w += 256) {
        int n = w >> 3, q = w & 7;
        *(uint4*)&sm[ZBH + n * 36 + 4 * q] = s4[w];
        *(uint4*)&sm[ZBL + n * 36 + 4 * q] = s4[1024 + w];
    }
}

// ===========================================================================
// Prep kernels
// ===========================================================================
__global__ void __launch_bounds__(256) conv_x_k(const float* __restrict__ x)
{
    __shared__ float smT[128 * 66];
    int tile = blockIdx.x, tid = threadIdx.x;
    const float* xp = x + (size_t)tile * 8192;
    uint32_t* da = g_xA + (size_t)tile * 8192;
    for (int w = tid; w < 4096; w += 256) {
        int r = w >> 6, kp = w & 63;
        float2 v = *(const float2*)(xp + r * NN + 2 * kp);
        da[w]        = pack_hi2(v.x, v.y);
        da[4096 + w] = pack_lo2(v.x, v.y);
    }
    for (int i = tid; i < 8192; i += 256) {
        int r = i >> 7, n = i & 127;
        smT[n * 66 + r] = xp[i];
    }
    __syncthreads();
    uint32_t* db = g_xB + (size_t)tile * 8192;
    for (int w = tid; w < 4096; w += 256) {
        int n = w >> 5, kpf = w & 31;
        float2 v = *(const float2*)&smT[n * 66 + 2 * kpf];
        db[w]        = pack_hi2(v.x, v.y);
        db[4096 + w] = pack_lo2(v.x, v.y);
    }
}

__global__ void __launch_bounds__(256) conv_H_k(const float* __restrict__ H)
{
    int tid = threadIdx.x;
    for (int w = tid; w < 8 * 2048; w += 256) {
        int c = w >> 11, o = (w >> 5) & 63, kpf = w & 31;
        int e = c >> 2, k = c & 3;
        int off = e * 256 + k * 64;
        float a  = H[o * 512 + off + 2 * kpf];
        float b2 = H[o * 512 + off + 2 * kpf + 1];
        g_HA[c * 4096 + o * 32 + kpf]        = pack_hi2(a, b2);
        g_HA[c * 4096 + 2048 + o * 32 + kpf] = pack_lo2(a, b2);
    }
}

__global__ void __launch_bounds__(256) y_init_k(const float* __restrict__ bias,
                                                float* __restrict__ y)
{
    int i = blockIdx.x * 256 + threadIdx.x;      // 8388608 total
    y[i] = bias[(i >> 7) & 63];
}

// ===========================================================================
// Persistent chain kernel: block = (b, e, 4-t chunk)
// ===========================================================================
__global__ void __launch_bounds__(256) chain_k(const float* __restrict__ S,
                                               float* __restrict__ y)
{
    extern __shared__ __align__(16) uint32_t sm[];
    int bi = blockIdx.x;
    int ch = bi & 15, e = (bi >> 4) & 1, b = bi >> 5;
    int t0 = ch * 4;
    int tid = threadIdx.x;
    int wid = tid >> 5, lane = tid & 31;
    int wm = wid & 3, wn = wid >> 2;
    int ra = lane >> 2, ca = lane & 3;

    uint32_t rawb = smem_u32(sm) + RAWW * 4u;

    #define SP(tt) (S + (size_t)(((b * 64 + (tt)) * 2) + e) * 16384)
    #define GXA(tt) (g_xA + (size_t)(b * 64 + (tt)) * 8192)
    #define GXB(tt) (g_xB + (size_t)(b * 64 + (tt)) * 8192)

    float macc[8][4];
    bool pf = false;

    // ---- warm-up: M2 = tap2[t0-1], M1 = tap1[t0-1] ----
    if (ch > 0) {
        fill_SB_direct(sm, SP(t0 - 2), tid);
        __syncthreads();
        mma_fullK_gA(sm, GXA(t0 - 3), macc, wm, wn, ra, ca);
        conv_A(sm, M2H, M2L, macc, wm, wn, ra, ca);
        __syncthreads();
        fill_SB_direct(sm, SP(t0 - 1), tid);
        __syncthreads();
        prefetch_S(rawb, SP(t0), tid);
        pf = true;
        mma_fullK_sA(sm, M2H, M2L, macc, wm, wn, ra, ca);
        __syncthreads();                       // all M2 reads done before overwrite
        conv_A(sm, M2H, M2L, macc, wm, wn, ra, ca);
        mma_fullK_gA(sm, GXA(t0 - 2), macc, wm, wn, ra, ca);
        conv_A(sm, M1H, M1L, macc, wm, wn, ra, ca);
    }

    for (int t = t0; t < t0 + 4; t++) {
        float accY[8][4];
        #pragma unroll
        for (int nt = 0; nt < 8; nt++)
            accY[nt][0] = accY[nt][1] = accY[nt][2] = accY[nt][3] = 0.f;

        if (t == 0) {
            prefetch_S(rawb, SP(1), tid);
            pf = true;
            copy_ZB(sm, GXB(0), tid);
            __syncthreads();
            mma_halfK_gH(sm, g_HA + (size_t)(e * 4) * 4096, accY, wm, wn, ra, ca);
            float* yp = y + (size_t)(b * 64) * 8192;
            int r0 = 16 * wm + ra;
            #pragma unroll
            for (int nt = 0; nt < 8; nt++) {
                int c = 64 * wn + nt * 8 + 2 * ca;
                atomicAdd(&yp[r0 * NN + c],           accY[nt][0]);
                atomicAdd(&yp[r0 * NN + c + 1],       accY[nt][1]);
                atomicAdd(&yp[(r0 + 8) * NN + c],     accY[nt][2]);
                atomicAdd(&yp[(r0 + 8) * NN + c + 1], accY[nt][3]);
            }
            continue;
        }

        // ---- S[b,t,e] into SB ----
        __syncthreads();                        // prior SB/ZB readers done
        if (pf) {
            CP_WAIT();
            __syncthreads();
            fill_SB_mixed(sm, SP(t), tid);
        } else {
            fill_SB_direct(sm, SP(t), tid);
        }
        __syncthreads();
        if (t + 1 < t0 + 4) { prefetch_S(rawb, SP(t + 1), tid); pf = true; }
        else pf = false;

        // ---- phase 3: m3 = M2 @ S, fold k=3 ----
        if (t >= 3) {
            mma_fullK_sA(sm, M2H, M2L, macc, wm, wn, ra, ca);
            conv_ZB(sm, macc, wm, wn, ra, ca);
            __syncthreads();
            mma_halfK_gH(sm, g_HA + (size_t)(e * 4 + 3) * 4096, accY, wm, wn, ra, ca);
        }
        // ---- phase 2: m2 = M1 @ S -> M2, fold k=2 ----
        if (t >= 2) {
            mma_fullK_sA(sm, M1H, M1L, macc, wm, wn, ra, ca);
            conv_A(sm, M2H, M2L, macc, wm, wn, ra, ca);
            __syncthreads();                    // phase3 ZB readers + M1 readers done
            conv_ZB(sm, macc, wm, wn, ra, ca);
            __syncthreads();
            mma_halfK_gH(sm, g_HA + (size_t)(e * 4 + 2) * 4096, accY, wm, wn, ra, ca);
        }
        // ---- phase 1: m1 = x[t-1] @ S -> M1, fold k=1 ----
        {
            mma_fullK_gA(sm, GXA(t - 1), macc, wm, wn, ra, ca);
            conv_A(sm, M1H, M1L, macc, wm, wn, ra, ca);
            __syncthreads();
            conv_ZB(sm, macc, wm, wn, ra, ca);
            __syncthreads();
            mma_halfK_gH(sm, g_HA + (size_t)(e * 4 + 1) * 4096, accY, wm, wn, ra, ca);
        }
        // ---- phase 0: fold k=0 (tap0 = x[t]) ----
        __syncthreads();
        copy_ZB(sm, GXB(t), tid);
        __syncthreads();
        mma_halfK_gH(sm, g_HA + (size_t)(e * 4) * 4096, accY, wm, wn, ra, ca);

        // ---- accumulate into y ----
        float* yp = y + (size_t)(b * 64 + t) * 8192;
        int r0 = 16 * wm + ra;
        #pragma unroll
        for (int nt = 0; nt < 8; nt++) {
            int c = 64 * wn + nt * 8 + 2 * ca;
            atomicAdd(&yp[r0 * NN + c],           accY[nt][0]);
            atomicAdd(&yp[r0 * NN + c + 1],       accY[nt][1]);
            atomicAdd(&yp[(r0 + 8) * NN + c],     accY[nt][2]);
            atomicAdd(&yp[(r0 + 8) * NN + c + 1], accY[nt][3]);
        }
    }
    #undef SP
    #undef GXA
    #undef GXB
}

// ---------------------------------------------------------------------------
extern "C" void kernel_launch(void* const* d_in, const int* in_sizes, int n_in,
                              void* d_out, int out_size)
{
    const float* x    = (const float*)d_in[0];
    const float* S    = (const float*)d_in[1];
    const float* H    = (const float*)d_in[2];
    const float* bias = (const float*)d_in[3];
    float* y = (float*)d_out;

    cudaFuncSetAttribute(chain_k, cudaFuncAttributeMaxDynamicSharedMemorySize,
                         SMWORDS * 4);

    conv_x_k<<<1024, 256>>>(x);
    conv_H_k<<<1, 256>>>(H);
    y_init_k<<<32768, 256>>>(bias, y);

    chain_k<<<512, 256, SMWORDS * 4>>>(S, y);
}

// round 7
// speedup vs baseline: 1.1623x; 1.0082x over previous
#include <cuda_runtime.h>
#include <cuda_bf16.h>
#include <cstdint>

#define NN 128

// ---- packed global operands (hi/lo bf16x2 planes) --------------------------
__device__ uint32_t g_xA[1024u * 8192u];  // x A-fmt  [tile(b,t)]: hi r*64+kp (4096), lo +4096
__device__ uint32_t g_xB[1024u * 8192u];  // x B64    [tile(b,t)]: hi n*32+kpf (4096), lo +4096
__device__ uint32_t g_HA[8u * 4096u];     // H chunks [e*4+k]: hi o*32+kpf (2048), lo +2048

// ---- smem word offsets -----------------------------------------------------
#define SBH  0          // S B-fmt hi: [128 n][stride 68]
#define SBL  8704
#define M1H  17408      // tap1 A-fmt hi: [64 r][stride 68]
#define M1L  21760
#define M2H  26112
#define M2L  30464
#define ZBH  34816      // tap B64: [128 n][stride 36]
#define ZBL  39424
#define RAWW 44032      // raw fp32 S rows 0..63: [64][128]
#define SMWORDS 52224   // 208896 bytes

// ---------------------------------------------------------------------------
__device__ __forceinline__ uint32_t pack_hi2(float a, float b) {
    uint32_t ua = (uint32_t)__bfloat16_as_ushort(__float2bfloat16(a));
    uint32_t ub = (uint32_t)__bfloat16_as_ushort(__float2bfloat16(b));
    return (ub << 16) | ua;
}
__device__ __forceinline__ uint32_t pack_lo2(float a, float b) {
    __nv_bfloat16 ha = __float2bfloat16(a);
    __nv_bfloat16 hb = __float2bfloat16(b);
    float ra = a - __bfloat162float(ha);
    float rb = b - __bfloat162float(hb);
    uint32_t ua = (uint32_t)__bfloat16_as_ushort(__float2bfloat16(ra));
    uint32_t ub = (uint32_t)__bfloat16_as_ushort(__float2bfloat16(rb));
    return (ub << 16) | ua;
}
__device__ __forceinline__ uint32_t smem_u32(const void* p) {
    uint32_t a;
    asm("{ .reg .u64 t; cvta.to.shared.u64 t, %1; cvt.u32.u64 %0, t; }" : "=r"(a) : "l"(p));
    return a;
}
__device__ __forceinline__ void ldsm4(uint32_t a, uint32_t& r0, uint32_t& r1,
                                      uint32_t& r2, uint32_t& r3) {
    asm volatile("ldmatrix.sync.aligned.m8n8.x4.shared.b16 {%0,%1,%2,%3}, [%4];"
                 : "=r"(r0), "=r"(r1), "=r"(r2), "=r"(r3) : "r"(a));
}

#define MMA_BF16(c, a0, a1, a2, a3, b0, b1)                                   \
    asm volatile(                                                             \
        "mma.sync.aligned.m16n8k16.row.col.f32.bf16.bf16.f32 "                \
        "{%0,%1,%2,%3}, {%4,%5,%6,%7}, {%8,%9}, {%0,%1,%2,%3};"               \
        : "+f"((c)[0]), "+f"((c)[1]), "+f"((c)[2]), "+f"((c)[3])              \
        : "r"(a0), "r"(a1), "r"(a2), "r"(a3), "r"(b0), "r"(b1))

// ---- S tile fills ----------------------------------------------------------
__device__ __forceinline__ void fill_SB_direct(uint32_t* sm, const float* __restrict__ Sp, int tid) {
    for (int i = tid; i < 8192; i += 256) {
        int n = i & 127, kp = i >> 7;
        float a = Sp[(2 * kp) * NN + n];
        float b = Sp[(2 * kp + 1) * NN + n];
        sm[SBH + n * 68 + kp] = pack_hi2(a, b);
        sm[SBL + n * 68 + kp] = pack_lo2(a, b);
    }
}
__device__ __forceinline__ void fill_SB_mixed(uint32_t* sm, const float* __restrict__ Sp, int tid) {
    const float* raw = (const float*)(sm + RAWW);
    for (int i = tid; i < 4096; i += 256) {
        int n = i & 127, kp = i >> 7;               // kp 0..31 from prefetched raw
        float a = raw[(2 * kp) * NN + n];
        float b = raw[(2 * kp + 1) * NN + n];
        sm[SBH + n * 68 + kp] = pack_hi2(a, b);
        sm[SBL + n * 68 + kp] = pack_lo2(a, b);
    }
    for (int i = tid; i < 4096; i += 256) {
        int n = i & 127, kp = 32 + (i >> 7);        // kp 32..63 from global
        float a = Sp[(2 * kp) * NN + n];
        float b = Sp[(2 * kp + 1) * NN + n];
        sm[SBH + n * 68 + kp] = pack_hi2(a, b);
        sm[SBL + n * 68 + kp] = pack_lo2(a, b);
    }
}
__device__ __forceinline__ void prefetch_S(uint32_t rawb, const float* __restrict__ src, int tid) {
    for (int w = tid; w < 2048; w += 256)
        asm volatile("cp.async.cg.shared.global [%0], [%1], 16;"
                     :: "r"(rawb + (uint32_t)w * 16u), "l"(src + 4 * w));
    asm volatile("cp.async.commit_group;");
}
#define CP_WAIT() asm volatile("cp.async.wait_group 0;" ::: "memory")

// ---- MMA cores (ldmatrix fragment loads) ----------------------------------
// acc = A(smem slot, stride 68) @ SB
__device__ __forceinline__ void mma_fullK_sA(uint32_t smb, int AHI, int ALO,
                                             float acc[8][4], int wm, int wn,
                                             int arow, int kcol)
{
    #pragma unroll
    for (int nt = 0; nt < 8; nt++)
        acc[nt][0] = acc[nt][1] = acc[nt][2] = acc[nt][3] = 0.f;
    uint32_t aH = smb + (uint32_t)((AHI + (16 * wm + arow) * 68 + kcol) * 4);
    uint32_t aL = smb + (uint32_t)((ALO + (16 * wm + arow) * 68 + kcol) * 4);
    uint32_t bH = smb + (uint32_t)((SBH + (64 * wn + arow) * 68 + kcol) * 4);
    uint32_t bL = smb + (uint32_t)((SBL + (64 * wn + arow) * 68 + kcol) * 4);
    #pragma unroll
    for (int k = 0; k < 8; k++) {
        uint32_t ah0, ah1, ah2, ah3, al0, al1, al2, al3;
        ldsm4(aH + k * 32, ah0, ah1, ah2, ah3);
        ldsm4(aL + k * 32, al0, al1, al2, al3);
        #pragma unroll
        for (int g = 0; g < 4; g++) {
            uint32_t b0e, b0o, b1e, b1o, c0e, c0o, c1e, c1o;
            ldsm4(bH + g * (16 * 68 * 4) + k * 32, b0e, b0o, b1e, b1o);
            ldsm4(bL + g * (16 * 68 * 4) + k * 32, c0e, c0o, c1e, c1o);
            MMA_BF16(acc[2 * g],     ah0, ah1, ah2, ah3, b0e, b1e);
            MMA_BF16(acc[2 * g],     ah0, ah1, ah2, ah3, c0e, c1e);
            MMA_BF16(acc[2 * g],     al0, al1, al2, al3, b0e, b1e);
            MMA_BF16(acc[2 * g + 1], ah0, ah1, ah2, ah3, b0o, b1o);
            MMA_BF16(acc[2 * g + 1], ah0, ah1, ah2, ah3, c0o, c1o);
            MMA_BF16(acc[2 * g + 1], al0, al1, al2, al3, b0o, b1o);
        }
    }
}
// acc = A(global g_xA tile, stride 64) @ SB
__device__ __forceinline__ void mma_fullK_gA(uint32_t smb, const uint32_t* __restrict__ gx,
                                             float acc[8][4], int wm, int wn,
                                             int arow, int kcol, int ra, int ca)
{
    #pragma unroll
    for (int nt = 0; nt < 8; nt++)
        acc[nt][0] = acc[nt][1] = acc[nt][2] = acc[nt][3] = 0.f;
    uint32_t bH = smb + (uint32_t)((SBH + (64 * wn + arow) * 68 + kcol) * 4);
    uint32_t bL = smb + (uint32_t)((SBL + (64 * wn + arow) * 68 + kcol) * 4);
    #pragma unroll
    for (int k = 0; k < 8; k++) {
        int ab = (16 * wm + ra) * 64 + k * 8 + ca;
        uint32_t ah0 = gx[ab],        ah1 = gx[ab + 512];
        uint32_t ah2 = gx[ab + 4],    ah3 = gx[ab + 516];
        uint32_t al0 = gx[ab + 4096], al1 = gx[ab + 4608];
        uint32_t al2 = gx[ab + 4100], al3 = gx[ab + 4612];
        #pragma unroll
        for (int g = 0; g < 4; g++) {
            uint32_t b0e, b0o, b1e, b1o, c0e, c0o, c1e, c1o;
            ldsm4(bH + g * (16 * 68 * 4) + k * 32, b0e, b0o, b1e, b1o);
            ldsm4(bL + g * (16 * 68 * 4) + k * 32, c0e, c0o, c1e, c1o);
            MMA_BF16(acc[2 * g],     ah0, ah1, ah2, ah3, b0e, b1e);
            MMA_BF16(acc[2 * g],     ah0, ah1, ah2, ah3, c0e, c1e);
            MMA_BF16(acc[2 * g],     al0, al1, al2, al3, b0e, b1e);
            MMA_BF16(acc[2 * g + 1], ah0, ah1, ah2, ah3, b0o, b1o);
            MMA_BF16(acc[2 * g + 1], ah0, ah1, ah2, ah3, c0o, c1o);
            MMA_BF16(acc[2 * g + 1], al0, al1, al2, al3, b0o, b1o);
        }
    }
}
// accY += H-chunk(global, stride 32) @ ZB(smem, stride 36)
__device__ __forceinline__ void mma_halfK_gH(uint32_t smb, const uint32_t* __restrict__ gh,
                                             float accY[8][4], int wm, int wn,
                                             int arow, int kcol, int ra, int ca)
{
    uint32_t bH = smb + (uint32_t)((ZBH + (64 * wn + arow) * 36 + kcol) * 4);
    uint32_t bL = smb + (uint32_t)((ZBL + (64 * wn + arow) * 36 + kcol) * 4);
    #pragma unroll
    for (int kk = 0; kk < 4; kk++) {
        int ab = (16 * wm + ra) * 32 + kk * 8 + ca;
        uint32_t ah0 = gh[ab],        ah1 = gh[ab + 256];
        uint32_t ah2 = gh[ab + 4],    ah3 = gh[ab + 260];
        uint32_t al0 = gh[ab + 2048], al1 = gh[ab + 2304];
        uint32_t al2 = gh[ab + 2052], al3 = gh[ab + 2308];
        #pragma unroll
        for (int g = 0; g < 4; g++) {
            uint32_t b0e, b0o, b1e, b1o, c0e, c0o, c1e, c1o;
            ldsm4(bH + g * (16 * 36 * 4) + kk * 32, b0e, b0o, b1e, b1o);
            ldsm4(bL + g * (16 * 36 * 4) + kk * 32, c0e, c0o, c1e, c1o);
            MMA_BF16(accY[2 * g],     ah0, ah1, ah2, ah3, b0e, b1e);
            MMA_BF16(accY[2 * g],     ah0, ah1, ah2, ah3, c0e, c1e);
            MMA_BF16(accY[2 * g],     al0, al1, al2, al3, b0e, b1e);
            MMA_BF16(accY[2 * g + 1], ah0, ah1, ah2, ah3, b0o, b1o);
            MMA_BF16(accY[2 * g + 1], ah0, ah1, ah2, ah3, c0o, c1o);
            MMA_BF16(accY[2 * g + 1], al0, al1, al2, al3, b0o, b1o);
        }
    }
}

// ---- acc -> smem staging ---------------------------------------------------
__device__ __forceinline__ void conv_A(uint32_t* sm, int AHI, int ALO,
                                       const float acc[8][4], int wm, int wn, int ra, int ca)
{
    int r0 = 16 * wm + ra;
    #pragma unroll
    for (int nt = 0; nt < 8; nt++) {
        int kp = 32 * wn + 4 * nt + ca;
        sm[AHI + r0 * 68 + kp]       = pack_hi2(acc[nt][0], acc[nt][1]);
        sm[ALO + r0 * 68 + kp]       = pack_lo2(acc[nt][0], acc[nt][1]);
        sm[AHI + (r0 + 8) * 68 + kp] = pack_hi2(acc[nt][2], acc[nt][3]);
        sm[ALO + (r0 + 8) * 68 + kp] = pack_lo2(acc[nt][2], acc[nt][3]);
    }
}
__device__ __forceinline__ void conv_ZB(uint32_t* sm, const float acc[8][4],
                                        int wm, int wn, int ra, int ca)
{
    #pragma unroll
    for (int nt = 0; nt < 8; nt++) {
        float o0 = __shfl_down_sync(0xffffffffu, acc[nt][0], 4);
        float o1 = __shfl_down_sync(0xffffffffu, acc[nt][1], 4);
        float o2 = __shfl_down_sync(0xffffffffu, acc[nt][2], 4);
        float o3 = __shfl_down_sync(0xffffffffu, acc[nt][3], 4);
        if (!(ra & 1)) {
            int c  = 64 * wn + nt * 8 + 2 * ca;
            int ka = 8 * wm + (ra >> 1);
            sm[ZBH + c * 36 + ka]           = pack_hi2(acc[nt][0], o0);
            sm[ZBL + c * 36 + ka]           = pack_lo2(acc[nt][0], o0);
            sm[ZBH + (c + 1) * 36 + ka]     = pack_hi2(acc[nt][1], o1);
            sm[ZBL + (c + 1) * 36 + ka]     = pack_lo2(acc[nt][1], o1);
            sm[ZBH + c * 36 + ka + 4]       = pack_hi2(acc[nt][2], o2);
            sm[ZBL + c * 36 + ka + 4]       = pack_lo2(acc[nt][2], o2);
            sm[ZBH + (c + 1) * 36 + ka + 4] = pack_hi2(acc[nt][3], o3);
            sm[ZBL + (c + 1) * 36 + ka + 4] = pack_lo2(acc[nt][3], o3);
        }
    }
}
__device__ __forceinline__ void copy_ZB(uint32_t* sm, const uint32_t* __restrict__ src, int tid) {
    const uint4* s4 = (const uint4*)src;
    for (int w = tid; w < 1024; w += 256) {
        int n = w >> 3, q = w & 7;
        *(uint4*)&sm[ZBH + n * 36 + 4 * q] = s4[w];
        *(uint4*)&sm[ZBL + n * 36 + 4 * q] = s4[1024 + w];
    }
}

// ===========================================================================
// Prep kernels
// ===========================================================================
__global__ void __launch_bounds__(256) conv_x_k(const float* __restrict__ x)
{
    __shared__ float smT[128 * 66];
    int tile = blockIdx.x, tid = threadIdx.x;
    const float* xp = x + (size_t)tile * 8192;
    uint32_t* da = g_xA + (size_t)tile * 8192;
    for (int w = tid; w < 4096; w += 256) {
        int r = w >> 6, kp = w & 63;
        float2 v = *(const float2*)(xp + r * NN + 2 * kp);
        da[w]        = pack_hi2(v.x, v.y);
        da[4096 + w] = pack_lo2(v.x, v.y);
    }
    for (int i = tid; i < 8192; i += 256) {
        int r = i >> 7, n = i & 127;
        smT[n * 66 + r] = xp[i];
    }
    __syncthreads();
    uint32_t* db = g_xB + (size_t)tile * 8192;
    for (int w = tid; w < 4096; w += 256) {
        int n = w >> 5, kpf = w & 31;
        float2 v = *(const float2*)&smT[n * 66 + 2 * kpf];
        db[w]        = pack_hi2(v.x, v.y);
        db[4096 + w] = pack_lo2(v.x, v.y);
    }
}

__global__ void __launch_bounds__(256) conv_H_k(const float* __restrict__ H)
{
    int tid = threadIdx.x;
    for (int w = tid; w < 8 * 2048; w += 256) {
        int c = w >> 11, o = (w >> 5) & 63, kpf = w & 31;
        int e = c >> 2, k = c & 3;
        int off = e * 256 + k * 64;
        float a  = H[o * 512 + off + 2 * kpf];
        float b2 = H[o * 512 + off + 2 * kpf + 1];
        g_HA[c * 4096 + o * 32 + kpf]        = pack_hi2(a, b2);
        g_HA[c * 4096 + 2048 + o * 32 + kpf] = pack_lo2(a, b2);
    }
}

__global__ void __launch_bounds__(256) y_init_k(const float* __restrict__ bias,
                                                float* __restrict__ y)
{
    int i = blockIdx.x * 256 + threadIdx.x;
    y[i] = bias[(i >> 7) & 63];
}

// ===========================================================================
// Persistent chain kernel: block = (b, e, 4-t chunk)
// ===========================================================================
__global__ void __launch_bounds__(256) chain_k(const float* __restrict__ S,
                                               float* __restrict__ y)
{
    extern __shared__ __align__(16) uint32_t sm[];
    int bi = blockIdx.x;
    int ch = bi & 15, e = (bi >> 4) & 1, b = bi >> 5;
    int t0 = ch * 4;
    int tid = threadIdx.x;
    int wid = tid >> 5, lane = tid & 31;
    int wm = wid & 3, wn = wid >> 2;
    int ra = lane >> 2, ca = lane & 3;
    int g = lane >> 3, lr = lane & 7;
    int arow = (g & 1) * 8 + lr;       // ldmatrix row offset within 16-block
    int kcol = (g >> 1) * 4;           // ldmatrix k-word offset

    uint32_t smb = smem_u32(sm);
    uint32_t rawb = smb + RAWW * 4u;

    #define SP(tt) (S + (size_t)(((b * 64 + (tt)) * 2) + e) * 16384)
    #define GXA(tt) (g_xA + (size_t)(b * 64 + (tt)) * 8192)
    #define GXB(tt) (g_xB + (size_t)(b * 64 + (tt)) * 8192)

    float macc[8][4];
    bool pf = false;

    // ---- warm-up: M2 = tap2[t0-1], M1 = tap1[t0-1] ----
    if (ch > 0) {
        fill_SB_direct(sm, SP(t0 - 2), tid);
        __syncthreads();
        mma_fullK_gA(smb, GXA(t0 - 3), macc, wm, wn, arow, kcol, ra, ca);
        conv_A(sm, M2H, M2L, macc, wm, wn, ra, ca);
        __syncthreads();
        fill_SB_direct(sm, SP(t0 - 1), tid);
        __syncthreads();
        prefetch_S(rawb, SP(t0), tid);
        pf = true;
        mma_fullK_sA(smb, M2H, M2L, macc, wm, wn, arow, kcol);
        __syncthreads();
        conv_A(sm, M2H, M2L, macc, wm, wn, ra, ca);
        mma_fullK_gA(smb, GXA(t0 - 2), macc, wm, wn, arow, kcol, ra, ca);
        conv_A(sm, M1H, M1L, macc, wm, wn, ra, ca);
    }

    for (int t = t0; t < t0 + 4; t++) {
        float accY[8][4];
        #pragma unroll
        for (int nt = 0; nt < 8; nt++)
            accY[nt][0] = accY[nt][1] = accY[nt][2] = accY[nt][3] = 0.f;

        if (t == 0) {
            prefetch_S(rawb, SP(1), tid);
            pf = true;
            copy_ZB(sm, GXB(0), tid);
            __syncthreads();
            mma_halfK_gH(smb, g_HA + (size_t)(e * 4) * 4096, accY, wm, wn, arow, kcol, ra, ca);
            float* yp = y + (size_t)(b * 64) * 8192;
            int r0 = 16 * wm + ra;
            #pragma unroll
            for (int nt = 0; nt < 8; nt++) {
                int c = 64 * wn + nt * 8 + 2 * ca;
                atomicAdd(&yp[r0 * NN + c],           accY[nt][0]);
                atomicAdd(&yp[r0 * NN + c + 1],       accY[nt][1]);
                atomicAdd(&yp[(r0 + 8) * NN + c],     accY[nt][2]);
                atomicAdd(&yp[(r0 + 8) * NN + c + 1], accY[nt][3]);
            }
            continue;
        }

        // ---- S[b,t,e] into SB ----
        __syncthreads();
        if (pf) {
            CP_WAIT();
            __syncthreads();
            fill_SB_mixed(sm, SP(t), tid);
        } else {
            fill_SB_direct(sm, SP(t), tid);
        }
        __syncthreads();
        if (t + 1 < t0 + 4) { prefetch_S(rawb, SP(t + 1), tid); pf = true; }
        else pf = false;

        // ---- phase 3: m3 = M2 @ S, fold k=3 ----
        if (t >= 3) {
            mma_fullK_sA(smb, M2H, M2L, macc, wm, wn, arow, kcol);
            conv_ZB(sm, macc, wm, wn, ra, ca);
            __syncthreads();
            mma_halfK_gH(smb, g_HA + (size_t)(e * 4 + 3) * 4096, accY, wm, wn, arow, kcol, ra, ca);
        }
        // ---- phase 2: m2 = M1 @ S -> M2, fold k=2 ----
        if (t >= 2) {
            mma_fullK_sA(smb, M1H, M1L, macc, wm, wn, arow, kcol);
            conv_A(sm, M2H, M2L, macc, wm, wn, ra, ca);
            __syncthreads();
            conv_ZB(sm, macc, wm, wn, ra, ca);
            __syncthreads();
            mma_halfK_gH(smb, g_HA + (size_t)(e * 4 + 2) * 4096, accY, wm, wn, arow, kcol, ra, ca);
        }
        // ---- phase 1: m1 = x[t-1] @ S -> M1, fold k=1 ----
        {
            mma_fullK_gA(smb, GXA(t - 1), macc, wm, wn, arow, kcol, ra, ca);
            conv_A(sm, M1H, M1L, macc, wm, wn, ra, ca);
            __syncthreads();
            conv_ZB(sm, macc, wm, wn, ra, ca);
            __syncthreads();
            mma_halfK_gH(smb, g_HA + (size_t)(e * 4 + 1) * 4096, accY, wm, wn, arow, kcol, ra, ca);
        }
        // ---- phase 0: fold k=0 (tap0 = x[t]) ----
        __syncthreads();
        copy_ZB(sm, GXB(t), tid);
        __syncthreads();
        mma_halfK_gH(smb, g_HA + (size_t)(e * 4) * 4096, accY, wm, wn, arow, kcol, ra, ca);

        // ---- accumulate into y ----
        float* yp = y + (size_t)(b * 64 + t) * 8192;
        int r0 = 16 * wm + ra;
        #pragma unroll
        for (int nt = 0; nt < 8; nt++) {
            int c = 64 * wn + nt * 8 + 2 * ca;
            atomicAdd(&yp[r0 * NN + c],           accY[nt][0]);
            atomicAdd(&yp[r0 * NN + c + 1],       accY[nt][1]);
            atomicAdd(&yp[(r0 + 8) * NN + c],     accY[nt][2]);
            atomicAdd(&yp[(r0 + 8) * NN + c + 1], accY[nt][3]);
        }
    }
    #undef SP
    #undef GXA
    #undef GXB
}

// ---------------------------------------------------------------------------
extern "C" void kernel_launch(void* const* d_in, const int* in_sizes, int n_in,
                              void* d_out, int out_size)
{
    const float* x    = (const float*)d_in[0];
    const float* S    = (const float*)d_in[1];
    const float* H    = (const float*)d_in[2];
    const float* bias = (const float*)d_in[3];
    float* y = (float*)d_out;

    cudaFuncSetAttribute(chain_k, cudaFuncAttributeMaxDynamicSharedMemorySize,
                         SMWORDS * 4);

    conv_x_k<<<1024, 256>>>(x);
    conv_H_k<<<1, 256>>>(H);
    y_init_k<<<32768, 256>>>(bias, y);

    chain_k<<<512, 256, SMWORDS * 4>>>(S, y);
}

// round 8
// speedup vs baseline: 1.1745x; 1.0105x over previous
#include <cuda_runtime.h>
#include <cuda_bf16.h>
#include <cstdint>

#define NN 128

// ---- packed global operands (hi/lo bf16x2 planes) --------------------------
__device__ uint32_t g_SB[2048u * 16384u]; // S B-fmt [tile(b,t,e)]: hi h0[0,4096) hi h1[4096,8192) lo h0[8192..) lo h1[12288..)
__device__ uint32_t g_xA[1024u * 8192u];  // x A-fmt [tile(b,t)]: hi r*64+kp (4096), lo +4096
__device__ uint32_t g_xB[1024u * 8192u];  // x B64   [tile(b,t)]: hi n*32+kpf (4096), lo +4096
__device__ uint32_t g_HA[8u * 4096u];     // H chunks [e*4+k]: hi o*32+kpf (2048), lo +2048

// ---- smem word offsets -----------------------------------------------------
#define M1H  0          // tap1 A-fmt hi: [64 r][stride 68]
#define M1L  4352
#define M2H  8704
#define M2L  13056
#define SBW0 17408      // S half-buffers: [128 n][stride 36] x {h0,h1} x {hi,lo}
                        // half h: hi at 17408+h*9216, lo at 22016+h*9216
#define ZBH  35840      // tap B64: [128 n][stride 36]
#define ZBL  40448
#define SMWORDS 45056   // 180224 bytes

// ---------------------------------------------------------------------------
__device__ __forceinline__ uint32_t pack_hi2(float a, float b) {
    uint32_t ua = (uint32_t)__bfloat16_as_ushort(__float2bfloat16(a));
    uint32_t ub = (uint32_t)__bfloat16_as_ushort(__float2bfloat16(b));
    return (ub << 16) | ua;
}
__device__ __forceinline__ uint32_t pack_lo2(float a, float b) {
    __nv_bfloat16 ha = __float2bfloat16(a);
    __nv_bfloat16 hb = __float2bfloat16(b);
    float ra = a - __bfloat162float(ha);
    float rb = b - __bfloat162float(hb);
    uint32_t ua = (uint32_t)__bfloat16_as_ushort(__float2bfloat16(ra));
    uint32_t ub = (uint32_t)__bfloat16_as_ushort(__float2bfloat16(rb));
    return (ub << 16) | ua;
}
__device__ __forceinline__ uint32_t smem_u32(const void* p) {
    uint32_t a;
    asm("{ .reg .u64 t; cvta.to.shared.u64 t, %1; cvt.u32.u64 %0, t; }" : "=r"(a) : "l"(p));
    return a;
}
__device__ __forceinline__ void ldsm4(uint32_t a, uint32_t& r0, uint32_t& r1,
                                      uint32_t& r2, uint32_t& r3) {
    asm volatile("ldmatrix.sync.aligned.m8n8.x4.shared.b16 {%0,%1,%2,%3}, [%4];"
                 : "=r"(r0), "=r"(r1), "=r"(r2), "=r"(r3) : "r"(a));
}

#define MMA_BF16(c, a0, a1, a2, a3, b0, b1)                                   \
    asm volatile(                                                             \
        "mma.sync.aligned.m16n8k16.row.col.f32.bf16.bf16.f32 "                \
        "{%0,%1,%2,%3}, {%4,%5,%6,%7}, {%8,%9}, {%0,%1,%2,%3};"               \
        : "+f"((c)[0]), "+f"((c)[1]), "+f"((c)[2]), "+f"((c)[3])              \
        : "r"(a0), "r"(a1), "r"(a2), "r"(a3), "r"(b0), "r"(b1))

// ---- async S-tile delivery -------------------------------------------------
__device__ __forceinline__ void prefetch_tile(uint32_t smb, const uint32_t* __restrict__ src,
                                              int tid) {
    #pragma unroll
    for (int h = 0; h < 2; h++) {
        uint32_t dh = smb + (uint32_t)((17408 + h * 9216) * 4);
        uint32_t dl = smb + (uint32_t)((22016 + h * 9216) * 4);
        const uint32_t* sh = src + h * 4096;
        const uint32_t* sl = src + 8192 + h * 4096;
        for (int w = tid; w < 1024; w += 256) {
            uint32_t off = (uint32_t)(((w >> 3) * 36 + (w & 7) * 4) * 4);
            asm volatile("cp.async.cg.shared.global [%0], [%1], 16;"
                         :: "r"(dh + off), "l"(sh + 4 * w));
            asm volatile("cp.async.cg.shared.global [%0], [%1], 16;"
                         :: "r"(dl + off), "l"(sl + 4 * w));
        }
    }
    asm volatile("cp.async.commit_group;");
}
#define CP_WAIT() asm volatile("cp.async.wait_group 0;" ::: "memory")

// ---- MMA cores -------------------------------------------------------------
// acc = A(smem M-slot, stride 68) @ S(half-buffers, stride 36)
__device__ __forceinline__ void mma_fullK_sA(uint32_t smb, int AHI, int ALO,
                                             float acc[8][4], int wm, int wn,
                                             int arow, int kcol)
{
    #pragma unroll
    for (int nt = 0; nt < 8; nt++)
        acc[nt][0] = acc[nt][1] = acc[nt][2] = acc[nt][3] = 0.f;
    uint32_t aH = smb + (uint32_t)((AHI + (16 * wm + arow) * 68 + kcol) * 4);
    uint32_t aL = smb + (uint32_t)((ALO + (16 * wm + arow) * 68 + kcol) * 4);
    #pragma unroll
    for (int h = 0; h < 2; h++) {
        uint32_t bH = smb + (uint32_t)((17408 + h * 9216 + (64 * wn + arow) * 36 + kcol) * 4);
        uint32_t bL = smb + (uint32_t)((22016 + h * 9216 + (64 * wn + arow) * 36 + kcol) * 4);
        #pragma unroll
        for (int kk = 0; kk < 4; kk++) {
            int k = 4 * h + kk;
            uint32_t ah0, ah1, ah2, ah3, al0, al1, al2, al3;
            ldsm4(aH + k * 32, ah0, ah1, ah2, ah3);
            ldsm4(aL + k * 32, al0, al1, al2, al3);
            #pragma unroll
            for (int g = 0; g < 4; g++) {
                uint32_t b0e, b0o, b1e, b1o, c0e, c0o, c1e, c1o;
                ldsm4(bH + g * (16 * 36 * 4) + kk * 32, b0e, b0o, b1e, b1o);
                ldsm4(bL + g * (16 * 36 * 4) + kk * 32, c0e, c0o, c1e, c1o);
                MMA_BF16(acc[2 * g],     ah0, ah1, ah2, ah3, b0e, b1e);
                MMA_BF16(acc[2 * g],     ah0, ah1, ah2, ah3, c0e, c1e);
                MMA_BF16(acc[2 * g],     al0, al1, al2, al3, b0e, b1e);
                MMA_BF16(acc[2 * g + 1], ah0, ah1, ah2, ah3, b0o, b1o);
                MMA_BF16(acc[2 * g + 1], ah0, ah1, ah2, ah3, c0o, c1o);
                MMA_BF16(acc[2 * g + 1], al0, al1, al2, al3, b0o, b1o);
            }
        }
    }
}
// acc = A(global g_xA tile) @ S(half-buffers)
__device__ __forceinline__ void mma_fullK_gA(uint32_t smb, const uint32_t* __restrict__ gx,
                                             float acc[8][4], int wm, int wn,
                                             int arow, int kcol, int ra, int ca)
{
    #pragma unroll
    for (int nt = 0; nt < 8; nt++)
        acc[nt][0] = acc[nt][1] = acc[nt][2] = acc[nt][3] = 0.f;
    #pragma unroll
    for (int h = 0; h < 2; h++) {
        uint32_t bH = smb + (uint32_t)((17408 + h * 9216 + (64 * wn + arow) * 36 + kcol) * 4);
        uint32_t bL = smb + (uint32_t)((22016 + h * 9216 + (64 * wn + arow) * 36 + kcol) * 4);
        #pragma unroll
        for (int kk = 0; kk < 4; kk++) {
            int k = 4 * h + kk;
            int ab = (16 * wm + ra) * 64 + k * 8 + ca;
            uint32_t ah0 = gx[ab],        ah1 = gx[ab + 512];
            uint32_t ah2 = gx[ab + 4],    ah3 = gx[ab + 516];
            uint32_t al0 = gx[ab + 4096], al1 = gx[ab + 4608];
            uint32_t al2 = gx[ab + 4100], al3 = gx[ab + 4612];
            #pragma unroll
            for (int g = 0; g < 4; g++) {
                uint32_t b0e, b0o, b1e, b1o, c0e, c0o, c1e, c1o;
                ldsm4(bH + g * (16 * 36 * 4) + kk * 32, b0e, b0o, b1e, b1o);
                ldsm4(bL + g * (16 * 36 * 4) + kk * 32, c0e, c0o, c1e, c1o);
                MMA_BF16(acc[2 * g],     ah0, ah1, ah2, ah3, b0e, b1e);
                MMA_BF16(acc[2 * g],     ah0, ah1, ah2, ah3, c0e, c1e);
                MMA_BF16(acc[2 * g],     al0, al1, al2, al3, b0e, b1e);
                MMA_BF16(acc[2 * g + 1], ah0, ah1, ah2, ah3, b0o, b1o);
                MMA_BF16(acc[2 * g + 1], ah0, ah1, ah2, ah3, c0o, c1o);
                MMA_BF16(acc[2 * g + 1], al0, al1, al2, al3, b0o, b1o);
            }
        }
    }
}
// accY += H-chunk(global, stride 32) @ ZB(smem, stride 36)
__device__ __forceinline__ void mma_halfK_gH(uint32_t smb, const uint32_t* __restrict__ gh,
                                             float accY[8][4], int wm, int wn,
                                             int arow, int kcol, int ra, int ca)
{
    uint32_t bH = smb + (uint32_t)((ZBH + (64 * wn + arow) * 36 + kcol) * 4);
    uint32_t bL = smb + (uint32_t)((ZBL + (64 * wn + arow) * 36 + kcol) * 4);
    #pragma unroll
    for (int kk = 0; kk < 4; kk++) {
        int ab = (16 * wm + ra) * 32 + kk * 8 + ca;
        uint32_t ah0 = gh[ab],        ah1 = gh[ab + 256];
        uint32_t ah2 = gh[ab + 4],    ah3 = gh[ab + 260];
        uint32_t al0 = gh[ab + 2048], al1 = gh[ab + 2304];
        uint32_t al2 = gh[ab + 2052], al3 = gh[ab + 2308];
        #pragma unroll
        for (int g = 0; g < 4; g++) {
            uint32_t b0e, b0o, b1e, b1o, c0e, c0o, c1e, c1o;
            ldsm4(bH + g * (16 * 36 * 4) + kk * 32, b0e, b0o, b1e, b1o);
            ldsm4(bL + g * (16 * 36 * 4) + kk * 32, c0e, c0o, c1e, c1o);
            MMA_BF16(accY[2 * g],     ah0, ah1, ah2, ah3, b0e, b1e);
            MMA_BF16(accY[2 * g],     ah0, ah1, ah2, ah3, c0e, c1e);
            MMA_BF16(accY[2 * g],     al0, al1, al2, al3, b0e, b1e);
            MMA_BF16(accY[2 * g + 1], ah0, ah1, ah2, ah3, b0o, b1o);
            MMA_BF16(accY[2 * g + 1], ah0, ah1, ah2, ah3, c0o, c1o);
            MMA_BF16(accY[2 * g + 1], al0, al1, al2, al3, b0o, b1o);
        }
    }
}

// ---- acc -> smem staging ---------------------------------------------------
__device__ __forceinline__ void conv_A(uint32_t* sm, int AHI, int ALO,
                                       const float acc[8][4], int wm, int wn, int ra, int ca)
{
    int r0 = 16 * wm + ra;
    #pragma unroll
    for (int nt = 0; nt < 8; nt++) {
        int kp = 32 * wn + 4 * nt + ca;
        sm[AHI + r0 * 68 + kp]       = pack_hi2(acc[nt][0], acc[nt][1]);
        sm[ALO + r0 * 68 + kp]       = pack_lo2(acc[nt][0], acc[nt][1]);
        sm[AHI + (r0 + 8) * 68 + kp] = pack_hi2(acc[nt][2], acc[nt][3]);
        sm[ALO + (r0 + 8) * 68 + kp] = pack_lo2(acc[nt][2], acc[nt][3]);
    }
}
__device__ __forceinline__ void conv_ZB(uint32_t* sm, const float acc[8][4],
                                        int wm, int wn, int ra, int ca)
{
    #pragma unroll
    for (int nt = 0; nt < 8; nt++) {
        float o0 = __shfl_down_sync(0xffffffffu, acc[nt][0], 4);
        float o1 = __shfl_down_sync(0xffffffffu, acc[nt][1], 4);
        float o2 = __shfl_down_sync(0xffffffffu, acc[nt][2], 4);
        float o3 = __shfl_down_sync(0xffffffffu, acc[nt][3], 4);
        if (!(ra & 1)) {
            int c  = 64 * wn + nt * 8 + 2 * ca;
            int ka = 8 * wm + (ra >> 1);
            sm[ZBH + c * 36 + ka]           = pack_hi2(acc[nt][0], o0);
            sm[ZBL + c * 36 + ka]           = pack_lo2(acc[nt][0], o0);
            sm[ZBH + (c + 1) * 36 + ka]     = pack_hi2(acc[nt][1], o1);
            sm[ZBL + (c + 1) * 36 + ka]     = pack_lo2(acc[nt][1], o1);
            sm[ZBH + c * 36 + ka + 4]       = pack_hi2(acc[nt][2], o2);
            sm[ZBL + c * 36 + ka + 4]       = pack_lo2(acc[nt][2], o2);
            sm[ZBH + (c + 1) * 36 + ka + 4] = pack_hi2(acc[nt][3], o3);
            sm[ZBL + (c + 1) * 36 + ka + 4] = pack_lo2(acc[nt][3], o3);
        }
    }
}
__device__ __forceinline__ void copy_ZB(uint32_t* sm, const uint32_t* __restrict__ src, int tid) {
    const uint4* s4 = (const uint4*)src;
    for (int w = tid; w < 1024; w += 256) {
        int n = w >> 3, q = w & 7;
        *(uint4*)&sm[ZBH + n * 36 + 4 * q] = s4[w];
        *(uint4*)&sm[ZBL + n * 36 + 4 * q] = s4[1024 + w];
    }
}

// ===========================================================================
// Prep kernels
// ===========================================================================
__global__ void __launch_bounds__(256) conv_S_k(const float* __restrict__ S)
{
    extern __shared__ __align__(16) char smraw[];
    float* smT = (float*)smraw;                 // [128][130]
    int tile = blockIdx.x, tid = threadIdx.x;
    const float* Sp = S + (size_t)tile * 16384;
    for (int i = tid; i < 16384; i += 256) {
        int j = i >> 7, n = i & 127;
        smT[n * 130 + j] = Sp[i];
    }
    __syncthreads();
    uint32_t* dst = g_SB + (size_t)tile * 16384;
    for (int w = tid; w < 8192; w += 256) {
        int n = w >> 6, kp = w & 63;
        float2 v = *(const float2*)&smT[n * 130 + 2 * kp];
        int idx = (kp >> 5) * 4096 + n * 32 + (kp & 31);
        dst[idx]        = pack_hi2(v.x, v.y);
        dst[8192 + idx] = pack_lo2(v.x, v.y);
    }
}

__global__ void __launch_bounds__(256) conv_x_k(const float* __restrict__ x)
{
    __shared__ float smT[128 * 66];
    int tile = blockIdx.x, tid = threadIdx.x;
    const float* xp = x + (size_t)tile * 8192;
    uint32_t* da = g_xA + (size_t)tile * 8192;
    for (int w = tid; w < 4096; w += 256) {
        int r = w >> 6, kp = w & 63;
        float2 v = *(const float2*)(xp + r * NN + 2 * kp);
        da[w]        = pack_hi2(v.x, v.y);
        da[4096 + w] = pack_lo2(v.x, v.y);
    }
    for (int i = tid; i < 8192; i += 256) {
        int r = i >> 7, n = i & 127;
        smT[n * 66 + r] = xp[i];
    }
    __syncthreads();
    uint32_t* db = g_xB + (size_t)tile * 8192;
    for (int w = tid; w < 4096; w += 256) {
        int n = w >> 5, kpf = w & 31;
        float2 v = *(const float2*)&smT[n * 66 + 2 * kpf];
        db[w]        = pack_hi2(v.x, v.y);
        db[4096 + w] = pack_lo2(v.x, v.y);
    }
}

__global__ void __launch_bounds__(256) conv_H_k(const float* __restrict__ H)
{
    int tid = threadIdx.x;
    for (int w = tid; w < 8 * 2048; w += 256) {
        int c = w >> 11, o = (w >> 5) & 63, kpf = w & 31;
        int e = c >> 2, k = c & 3;
        int off = e * 256 + k * 64;
        float a  = H[o * 512 + off + 2 * kpf];
        float b2 = H[o * 512 + off + 2 * kpf + 1];
        g_HA[c * 4096 + o * 32 + kpf]        = pack_hi2(a, b2);
        g_HA[c * 4096 + 2048 + o * 32 + kpf] = pack_lo2(a, b2);
    }
}

__global__ void __launch_bounds__(256) y_init_k(const float* __restrict__ bias,
                                                float* __restrict__ y)
{
    int i = blockIdx.x * 256 + threadIdx.x;
    y[i] = bias[(i >> 7) & 63];
}

// ===========================================================================
// Persistent chain kernel: block = (b, e, 4-t chunk)
// ===========================================================================
__global__ void __launch_bounds__(256) chain_k(float* __restrict__ y)
{
    extern __shared__ __align__(16) uint32_t sm[];
    int bi = blockIdx.x;
    int ch = bi & 15, e = (bi >> 4) & 1, b = bi >> 5;
    int t0 = ch * 4;
    int tid = threadIdx.x;
    int wid = tid >> 5, lane = tid & 31;
    int wm = wid & 3, wn = wid >> 2;
    int ra = lane >> 2, ca = lane & 3;
    int g = lane >> 3, lr = lane & 7;
    int arow = (g & 1) * 8 + lr;
    int kcol = (g >> 1) * 4;

    uint32_t smb = smem_u32(sm);

    #define GSB(tt) (g_SB + (size_t)(((b * 64 + (tt)) * 2) + e) * 16384)
    #define GXA(tt) (g_xA + (size_t)(b * 64 + (tt)) * 8192)
    #define GXB(tt) (g_xB + (size_t)(b * 64 + (tt)) * 8192)

    float macc[8][4];

    // ---- warm-up: build M2 = tap2[t0-1], M1 = tap1[t0-1] ----
    if (ch > 0) {
        prefetch_tile(smb, GSB(t0 - 2), tid);
        CP_WAIT();
        __syncthreads();
        mma_fullK_gA(smb, GXA(t0 - 3), macc, wm, wn, arow, kcol, ra, ca);
        conv_A(sm, M2H, M2L, macc, wm, wn, ra, ca);
        __syncthreads();
        prefetch_tile(smb, GSB(t0 - 1), tid);
        CP_WAIT();
        __syncthreads();
        mma_fullK_sA(smb, M2H, M2L, macc, wm, wn, arow, kcol);
        __syncthreads();
        conv_A(sm, M2H, M2L, macc, wm, wn, ra, ca);
        mma_fullK_gA(smb, GXA(t0 - 2), macc, wm, wn, arow, kcol, ra, ca);
        conv_A(sm, M1H, M1L, macc, wm, wn, ra, ca);
        __syncthreads();
        prefetch_tile(smb, GSB(t0), tid);
    } else {
        prefetch_tile(smb, GSB(1), tid);
    }

    for (int t = t0; t < t0 + 4; t++) {
        float accY[8][4];
        #pragma unroll
        for (int nt = 0; nt < 8; nt++)
            accY[nt][0] = accY[nt][1] = accY[nt][2] = accY[nt][3] = 0.f;

        if (t == 0) {
            copy_ZB(sm, GXB(0), tid);
            __syncthreads();
            mma_halfK_gH(smb, g_HA + (size_t)(e * 4) * 4096, accY, wm, wn, arow, kcol, ra, ca);
            float* yp = y + (size_t)(b * 64) * 8192;
            int r0 = 16 * wm + ra;
            #pragma unroll
            for (int nt = 0; nt < 8; nt++) {
                int c = 64 * wn + nt * 8 + 2 * ca;
                atomicAdd(&yp[r0 * NN + c],           accY[nt][0]);
                atomicAdd(&yp[r0 * NN + c + 1],       accY[nt][1]);
                atomicAdd(&yp[(r0 + 8) * NN + c],     accY[nt][2]);
                atomicAdd(&yp[(r0 + 8) * NN + c + 1], accY[nt][3]);
            }
            continue;
        }

        CP_WAIT();            // S[t] halves resident
        __syncthreads();      // also: prev fold0 ZB readers done

        // ---- phase 3: m3 = M2 @ S, fold k=3 ----
        if (t >= 3) {
            mma_fullK_sA(smb, M2H, M2L, macc, wm, wn, arow, kcol);
            conv_ZB(sm, macc, wm, wn, ra, ca);
            __syncthreads();
            mma_halfK_gH(smb, g_HA + (size_t)(e * 4 + 3) * 4096, accY, wm, wn, arow, kcol, ra, ca);
        }
        // ---- phase 2: m2 = M1 @ S -> M2, fold k=2 ----
        if (t >= 2) {
            mma_fullK_sA(smb, M1H, M1L, macc, wm, wn, arow, kcol);
            conv_A(sm, M2H, M2L, macc, wm, wn, ra, ca);
            __syncthreads();
            conv_ZB(sm, macc, wm, wn, ra, ca);
            __syncthreads();
            mma_halfK_gH(smb, g_HA + (size_t)(e * 4 + 2) * 4096, accY, wm, wn, arow, kcol, ra, ca);
        }
        // ---- phase 1: m1 = x[t-1] @ S -> M1, fold k=1 ----
        {
            mma_fullK_gA(smb, GXA(t - 1), macc, wm, wn, arow, kcol, ra, ca);
            conv_A(sm, M1H, M1L, macc, wm, wn, ra, ca);
            __syncthreads();                         // all warps past last SB read
            if (t < t0 + 3) prefetch_tile(smb, GSB(t + 1), tid);
            conv_ZB(sm, macc, wm, wn, ra, ca);
            __syncthreads();
            mma_halfK_gH(smb, g_HA + (size_t)(e * 4 + 1) * 4096, accY, wm, wn, arow, kcol, ra, ca);
        }
        // ---- phase 0: fold k=0 (tap0 = x[t]) ----
        __syncthreads();
        copy_ZB(sm, GXB(t), tid);
        __syncthreads();
        mma_halfK_gH(smb, g_HA + (size_t)(e * 4) * 4096, accY, wm, wn, arow, kcol, ra, ca);

        // ---- accumulate into y ----
        float* yp = y + (size_t)(b * 64 + t) * 8192;
        int r0 = 16 * wm + ra;
        #pragma unroll
        for (int nt = 0; nt < 8; nt++) {
            int c = 64 * wn + nt * 8 + 2 * ca;
            atomicAdd(&yp[r0 * NN + c],           accY[nt][0]);
            atomicAdd(&yp[r0 * NN + c + 1],       accY[nt][1]);
            atomicAdd(&yp[(r0 + 8) * NN + c],     accY[nt][2]);
            atomicAdd(&yp[(r0 + 8) * NN + c + 1], accY[nt][3]);
        }
    }
    #undef GSB
    #undef GXA
    #undef GXB
}

// ---------------------------------------------------------------------------
extern "C" void kernel_launch(void* const* d_in, const int* in_sizes, int n_in,
                              void* d_out, int out_size)
{
    const float* x    = (const float*)d_in[0];
    const float* S    = (const float*)d_in[1];
    const float* H    = (const float*)d_in[2];
    const float* bias = (const float*)d_in[3];
    float* y = (float*)d_out;

    cudaFuncSetAttribute(conv_S_k, cudaFuncAttributeMaxDynamicSharedMemorySize,
                         128 * 130 * 4);
    cudaFuncSetAttribute(chain_k, cudaFuncAttributeMaxDynamicSharedMemorySize,
                         SMWORDS * 4);

    conv_S_k<<<2048, 256, 128 * 130 * 4>>>(S);
    conv_x_k<<<1024, 256>>>(x);
    conv_H_k<<<1, 256>>>(H);
    y_init_k<<<32768, 256>>>(bias, y);

    chain_k<<<512, 256, SMWORDS * 4>>>(y);
}